// round 4
// baseline (speedup 1.0000x reference)
#include <cuda_runtime.h>
#include <stdint.h>

#define HH 2048
#define WW 2048
#define NPIX (HH*WW)
#define HBINS 2048
#define CAP 8192
#define NMS_EPS_F 1e-5f
#define SAM_EPS_F 1e-8f

// Scratch (device globals — no allocation allowed)
__device__ unsigned long long g_surv[NPIX];   // survivor keys
__device__ unsigned int g_hist[HBINS];
__device__ unsigned int g_nsurv;

__global__ void reset_kernel() {
    int t = blockIdx.x * blockDim.x + threadIdx.x;
    if (t < HBINS) g_hist[t] = 0u;
    if (t == 0) g_nsurv = 0u;
}

__device__ __forceinline__ int val_bin(float v) {
    int b = (int)(v * (float)HBINS);
    if (b > HBINS - 1) b = HBINS - 1;
    if (b < 0) b = 0;
    return b;
}

// Pass 1: 3x3 NMS + cross-scale + border test; survivors appended to g_surv
// (block-aggregated) and histogrammed (global atomics, ~116k total).
// Each thread computes 4 consecutive pixels in x via float4 loads.
__global__ void nms_surv_kernel(const float* __restrict__ low,
                                const float* __restrict__ cur,
                                const float* __restrict__ high) {
    __shared__ unsigned long long slist[1024];
    __shared__ unsigned int scount;
    __shared__ unsigned int sbase;
    int lt = threadIdx.y * blockDim.x + threadIdx.x;
    if (lt == 0) scount = 0u;
    __syncthreads();

    int x0 = (blockIdx.x * blockDim.x + threadIdx.x) * 4;
    int y  = blockIdx.y * blockDim.y + threadIdx.y;

    if (y >= 3 && y < HH - 3) {
        // 3 rows of 6 values each: [x0-1, x0..x0+3, x0+4]
        float r[3][6];
        #pragma unroll
        for (int dy = 0; dy < 3; dy++) {
            const float* rowp = cur + (y + dy - 1) * WW;
            float4 c4 = *(const float4*)(rowp + x0);
            r[dy][0] = (x0 >= 1) ? rowp[x0 - 1] : 0.0f;
            r[dy][1] = c4.x; r[dy][2] = c4.y; r[dy][3] = c4.z; r[dy][4] = c4.w;
            r[dy][5] = (x0 + 4 < WW) ? rowp[x0 + 4] : 0.0f;
        }
        float4 l4 = *(const float4*)(low  + y * WW + x0);
        float4 h4 = *(const float4*)(high + y * WW + x0);
        float lv[4] = {l4.x, l4.y, l4.z, l4.w};
        float hv[4] = {h4.x, h4.y, h4.z, h4.w};

        #pragma unroll
        for (int j = 0; j < 4; j++) {
            int x = x0 + j;
            if (x < 3 || x >= WW - 3) continue;
            float c = r[1][j + 1];
            float m = c;
            #pragma unroll
            for (int dy = 0; dy < 3; dy++) {
                m = fmaxf(m, fmaxf(r[dy][j], fmaxf(r[dy][j + 1], r[dy][j + 2])));
            }
            // same float expression as reference: (cur - mp + 1e-5) > 0
            if ((c - m + NMS_EPS_F) > 0.0f && c > lv[j] && c > hv[j]) {
                unsigned int idx = (unsigned int)(y * WW + x);
                unsigned long long key =
                    ((unsigned long long)__float_as_uint(c) << 32) |
                    (unsigned long long)(0xFFFFFFFFu - idx);
                unsigned int p = atomicAdd(&scount, 1u);
                slist[p] = key;
            }
        }
    }
    __syncthreads();
    unsigned int cnt = scount;
    if (lt == 0 && cnt) sbase = atomicAdd(&g_nsurv, cnt);
    __syncthreads();
    int nth = blockDim.x * blockDim.y;
    for (unsigned int i = lt; i < cnt; i += nth) {
        unsigned long long key = slist[i];
        unsigned int dst = sbase + i;
        if (dst < (unsigned int)NPIX) g_surv[dst] = key;
        float v = __uint_as_float((unsigned int)(key >> 32));
        atomicAdd(&g_hist[val_bin(v)], 1u);
    }
}

// Final: (a) suffix-scan histogram for threshold bin B, (b) compact survivors
// with bin >= B into smem, (c) bitonic sort desc, (d) soft-argmax gather +
// output composition. One block, 1024 threads.
extern __shared__ unsigned long long skeys[];
__global__ void final_kernel(const float* __restrict__ low,
                             const float* __restrict__ cur,
                             const float* __restrict__ high,
                             float* __restrict__ out, int k) {
    __shared__ unsigned int suf[1024];
    __shared__ unsigned int sB, sPos;
    int t = threadIdx.x;
    int nt = blockDim.x;   // 1024
    if (t == 0) { sB = 0u; sPos = 0u; }

    // ---- threshold: max bin B with count(bins >= B) >= k ----
    unsigned int b0 = g_hist[2 * t];
    unsigned int b1 = g_hist[2 * t + 1];
    suf[t] = b0 + b1;
    __syncthreads();
    for (int off = 1; off < 1024; off <<= 1) {
        unsigned int add = (t + off < 1024) ? suf[t + off] : 0u;
        __syncthreads();
        suf[t] += add;
        __syncthreads();
    }
    unsigned int after = (t < 1023) ? suf[t + 1] : 0u;
    int best = -1;
    if (after + b1 >= (unsigned int)k) best = 2 * t + 1;
    else if (after + b1 + b0 >= (unsigned int)k) best = 2 * t;
    if (best >= 0) atomicMax(&sB, (unsigned int)best);

    for (int i = t; i < CAP; i += nt) skeys[i] = 0ULL;
    __syncthreads();
    unsigned int B = sB;

    // ---- compact survivors ----
    unsigned int n = g_nsurv;
    if (n > (unsigned int)NPIX) n = (unsigned int)NPIX;
    for (unsigned int i = t; i < n; i += nt) {
        unsigned long long key = g_surv[i];
        float v = __uint_as_float((unsigned int)(key >> 32));
        if ((unsigned int)val_bin(v) >= B) {
            unsigned int p = atomicAdd(&sPos, 1u);
            if (p < CAP) skeys[p] = key;
        }
    }
    __syncthreads();
    unsigned int nc = sPos;
    if (nc > CAP) nc = CAP;
    int S = (nc <= 4096) ? 4096 : 8192;

    // ---- bitonic sort descending over S (power of 2) ----
    for (int kk = 2; kk <= S; kk <<= 1) {
        for (int j = kk >> 1; j > 0; j >>= 1) {
            for (int i = t; i < S; i += nt) {
                int l = i ^ j;
                if (l > i) {
                    unsigned long long a = skeys[i];
                    unsigned long long b = skeys[l];
                    bool up = ((i & kk) == 0);
                    if (up ? (a < b) : (a > b)) { skeys[i] = b; skeys[l] = a; }
                }
            }
            __syncthreads();
        }
    }

    // ---- gather + compose ----
    for (int i = t; i < k; i += nt) {
        unsigned long long key = (i < S) ? skeys[i] : 0ULL;
        float val = __uint_as_float((unsigned int)(key >> 32));
        unsigned int idx = 0xFFFFFFFFu - (unsigned int)(key & 0xFFFFFFFFu);
        out[i] = val;
        float a = 0.0f, fx = 0.0f, fy = 0.0f;
        if (idx < (unsigned int)NPIX) {
            int y = (int)(idx / WW);
            int x = (int)(idx % WW);
            float tot = 0.0f, sl = 0.0f, shh = 0.0f, wy = 0.0f, wx = 0.0f;
            #pragma unroll
            for (int dy = -1; dy <= 1; dy++) {
                #pragma unroll
                for (int dx = -1; dx <= 1; dx++) {
                    int jdx = (y + dy) * WW + (x + dx);
                    float lv = low[jdx];
                    float cv = cur[jdx];
                    float hv = high[jdx];
                    float s3 = lv + cv + hv;
                    tot += s3;
                    sl  += lv;
                    shh += hv;
                    wy  += (float)dy * s3;
                    wx  += (float)dx * s3;
                }
            }
            float den = tot + SAM_EPS_F;
            float s = (shh - sl) / den;
            fy = ((float)y + wy / den) * (1.0f / (float)HH);
            fx = ((float)x + wx / den) * (1.0f / (float)WW);
            a = s * (1.0f / 2048.0f);   // MR_SIZE / min(H,W) * s
        }
        float* o = out + k + 6 * i;     // full_A row-major [k,2,3]
        o[0] = a;    o[1] = 0.0f; o[2] = fx;
        o[3] = 0.0f; o[4] = a;    o[5] = fy;
    }
}

extern "C" void kernel_launch(void* const* d_in, const int* in_sizes, int n_in,
                              void* d_out, int out_size) {
    const float* low  = (const float*)d_in[0];
    const float* cur  = (const float*)d_in[1];
    const float* high = (const float*)d_in[2];
    float* out = (float*)d_out;
    int k = out_size / 7;   // out = [topk(k); full_A(k*6)]
    if (k < 1) k = 1;

    reset_kernel<<<2, 1024>>>();

    dim3 bb(32, 8);                  // 4 px per thread in x -> tile 128x8
    dim3 gg(WW / 128, HH / 8);
    nms_surv_kernel<<<gg, bb>>>(low, cur, high);

    cudaFuncSetAttribute(final_kernel,
                         cudaFuncAttributeMaxDynamicSharedMemorySize,
                         CAP * (int)sizeof(unsigned long long));
    final_kernel<<<1, 1024, CAP * sizeof(unsigned long long)>>>(low, cur, high, out, k);
}

// round 15
// speedup vs baseline: 1.3785x; 1.3785x over previous
#include <cuda_runtime.h>
#include <stdint.h>

#define HH 2048
#define WW 2048
#define NPIX (HH*WW)
#define HBINS 2048
#define CAP 8192
#define SLCAP 4608
#define SURV_MAX (NPIX/2)
#define NMS_EPS_F 1e-5f
#define SAM_EPS_F 1e-8f

// Scratch (device globals — no allocation allowed)
__device__ unsigned long long g_surv[SURV_MAX];
__device__ unsigned long long g_cand[CAP];
__device__ unsigned int g_hist[HBINS];
__device__ unsigned int g_nsurv;
__device__ unsigned int g_ncand;
__device__ unsigned int g_bin;

__device__ __forceinline__ int val_bin(float v) {
    int b = (int)(v * (float)HBINS);
    if (b > HBINS - 1) b = HBINS - 1;
    if (b < 0) b = 0;
    return b;
}

__device__ __forceinline__ unsigned long long make_key(float v, unsigned int idx) {
    return ((unsigned long long)__float_as_uint(v) << 32) |
           (unsigned long long)(0xFFFFFFFFu - idx);
}

__global__ void reset_kernel() {
    int t = blockIdx.x * blockDim.x + threadIdx.x;
    if (t < HBINS) g_hist[t] = 0u;
    if (t == 0) { g_nsurv = 0u; g_ncand = 0u; g_bin = 0u; }
}

// Pass 1: each thread computes an 8px-wide x 8row-tall tile with a rolling
// separable 3x3 max. Survivors buffered in thread-local array, one smem
// atomic per thread, one global atomic per block. Histogram via global
// atomics at flush (~380k spread over 2048 bins).
__global__ void __launch_bounds__(256) nms_kernel(const float* __restrict__ low,
                                                  const float* __restrict__ cur,
                                                  const float* __restrict__ high) {
    __shared__ unsigned long long slist[SLCAP];
    __shared__ unsigned int scount;
    __shared__ unsigned int sbase;
    int t = threadIdx.x;
    if (t == 0) scount = 0u;
    __syncthreads();

    int x0 = t * 8;                 // 256 threads cover full width
    int y0 = blockIdx.x * 8;        // 256 blocks cover full height
    const bool xlo = (x0 == 0), xhi = (x0 + 8 == WW);

    float hmbuf[3][8];
    float cA[8], cB[8];
    unsigned long long tc[64];
    int tcn = 0;

#define LOADHM(RIDX, SLOT) do {                                              \
    float v[10];                                                             \
    int r_ = (RIDX);                                                         \
    if (r_ >= 0 && r_ < HH) {                                                \
        const float* rp = cur + r_ * WW + x0;                                \
        float4 a4 = *(const float4*)rp;                                      \
        float4 b4 = *(const float4*)(rp + 4);                                \
        v[0] = xlo ? 0.0f : rp[-1];                                          \
        v[1] = a4.x; v[2] = a4.y; v[3] = a4.z; v[4] = a4.w;                  \
        v[5] = b4.x; v[6] = b4.y; v[7] = b4.z; v[8] = b4.w;                  \
        v[9] = xhi ? 0.0f : rp[8];                                           \
    } else {                                                                 \
        _Pragma("unroll") for (int q = 0; q < 10; q++) v[q] = 0.0f;          \
    }                                                                        \
    float p[9];                                                              \
    _Pragma("unroll") for (int q = 0; q < 9; q++) p[q] = fmaxf(v[q], v[q+1]);\
    _Pragma("unroll") for (int q = 0; q < 8; q++)                            \
        hmbuf[SLOT][q] = fmaxf(p[q], v[q+2]);                                \
    _Pragma("unroll") for (int q = 0; q < 8; q++) cB[q] = v[q+1];            \
} while (0)

    LOADHM(y0 - 1, 0);
    LOADHM(y0,     1);
    #pragma unroll
    for (int q = 0; q < 8; q++) cA[q] = cB[q];

    #pragma unroll
    for (int rr = 0; rr < 8; rr++) {
        LOADHM(y0 + rr + 1, (rr + 2) % 3);
        int y = y0 + rr;
        if (y >= 3 && y < HH - 3) {
            #pragma unroll
            for (int j = 0; j < 8; j++) {
                float c = cA[j];
                float m = fmaxf(fmaxf(hmbuf[rr % 3][j], hmbuf[(rr + 1) % 3][j]),
                                hmbuf[(rr + 2) % 3][j]);
                // same float expression as reference: (cur - mp + 1e-5) > 0
                if ((c - m + NMS_EPS_F) > 0.0f) {
                    int x = x0 + j;
                    if (x >= 3 && x < WW - 3) {
                        int idx = y * WW + x;
                        if (c > __ldg(&low[idx]) && c > __ldg(&high[idx]))
                            tc[tcn++] = make_key(c, (unsigned int)idx);
                    }
                }
            }
        }
        #pragma unroll
        for (int q = 0; q < 8; q++) cA[q] = cB[q];
    }
#undef LOADHM

    if (tcn) {
        unsigned int p = atomicAdd(&scount, (unsigned int)tcn);
        for (int q = 0; q < tcn; q++)
            if (p + q < SLCAP) slist[p + q] = tc[q];
    }
    __syncthreads();
    unsigned int cnt = scount;
    if (cnt > SLCAP) cnt = SLCAP;
    if (t == 0 && cnt) sbase = atomicAdd(&g_nsurv, cnt);
    __syncthreads();
    for (unsigned int i = t; i < cnt; i += 256) {
        unsigned long long key = slist[i];
        unsigned int dst = sbase + i;
        if (dst < (unsigned int)SURV_MAX) g_surv[dst] = key;
        float v = __uint_as_float((unsigned int)(key >> 32));
        atomicAdd(&g_hist[val_bin(v)], 1u);
    }
}

// Threshold: max bin B with count(values in bins >= B) >= k.
__global__ void thresh_kernel(int k) {
    __shared__ unsigned int suf[1024];
    __shared__ unsigned int sB;
    int t = threadIdx.x;            // 1024 threads, 2 bins each
    if (t == 0) sB = 0u;
    unsigned int b0 = g_hist[2 * t];
    unsigned int b1 = g_hist[2 * t + 1];
    suf[t] = b0 + b1;
    __syncthreads();
    for (int off = 1; off < 1024; off <<= 1) {
        unsigned int add = (t + off < 1024) ? suf[t + off] : 0u;
        __syncthreads();
        suf[t] += add;
        __syncthreads();
    }
    unsigned int after = (t < 1023) ? suf[t + 1] : 0u;
    int best = -1;
    if (after + b1 >= (unsigned int)k) best = 2 * t + 1;
    else if (after + b1 + b0 >= (unsigned int)k) best = 2 * t;
    if (best >= 0) atomicMax(&sB, (unsigned int)best);
    __syncthreads();
    if (t == 0) g_bin = sB;
}

// Compact survivors with bin >= B into g_cand (warp-aggregated atomics).
__global__ void compact_kernel() {
    unsigned int B = g_bin;
    unsigned int n = g_nsurv;
    if (n > (unsigned int)SURV_MAX) n = (unsigned int)SURV_MAX;
    unsigned int stride = gridDim.x * blockDim.x;
    unsigned int lane = threadIdx.x & 31;
    unsigned int nloop = ((n + stride - 1) / stride) * stride;
    for (unsigned int i = blockIdx.x * blockDim.x + threadIdx.x; i < nloop; i += stride) {
        bool pass = false;
        unsigned long long key = 0ULL;
        if (i < n) {
            key = g_surv[i];
            float v = __uint_as_float((unsigned int)(key >> 32));
            pass = ((unsigned int)val_bin(v) >= B);
        }
        unsigned int mask = __ballot_sync(0xFFFFFFFFu, pass);
        if (mask) {
            int lead = __ffs(mask) - 1;
            unsigned int base = 0;
            if ((int)lane == lead) base = atomicAdd(&g_ncand, (unsigned int)__popc(mask));
            base = __shfl_sync(0xFFFFFFFFu, base, lead);
            unsigned int off = __popc(mask & ((1u << lane) - 1u));
            if (pass && base + off < CAP) g_cand[base + off] = key;
        }
    }
}

// Rank + output: each thread owns one candidate; rank = #keys strictly
// greater (keys unique -> exact sort order). rank<k writes out[rank].
extern __shared__ unsigned long long sk[];
__global__ void rank_kernel(const float* __restrict__ low,
                            const float* __restrict__ cur,
                            const float* __restrict__ high,
                            float* __restrict__ out, int k) {
    int t = threadIdx.x;
    int ncc = (int)g_ncand;
    if (ncc > CAP) ncc = CAP;
    for (int i = t; i < ncc; i += blockDim.x) sk[i] = g_cand[i];
    __syncthreads();

    int i = blockIdx.x * blockDim.x + t;
    unsigned long long my = (i < ncc) ? sk[i] : 0ULL;
    int rank = 0;
    #pragma unroll 8
    for (int j = 0; j < ncc; j++) rank += (sk[j] > my) ? 1 : 0;

    if (i < ncc && rank < k) {
        float val = __uint_as_float((unsigned int)(my >> 32));
        unsigned int idx = 0xFFFFFFFFu - (unsigned int)(my & 0xFFFFFFFFu);
        out[rank] = val;
        float a = 0.0f, fx = 0.0f, fy = 0.0f;
        if (idx < (unsigned int)NPIX) {
            int y = (int)(idx / WW);
            int x = (int)(idx % WW);
            float tot = 0.0f, sl = 0.0f, shh = 0.0f, wy = 0.0f, wx = 0.0f;
            #pragma unroll
            for (int dy = -1; dy <= 1; dy++) {
                #pragma unroll
                for (int dx = -1; dx <= 1; dx++) {
                    int jdx = (y + dy) * WW + (x + dx);
                    float lv = low[jdx];
                    float cv = cur[jdx];
                    float hv = high[jdx];
                    float s3 = lv + cv + hv;
                    tot += s3;
                    sl  += lv;
                    shh += hv;
                    wy  += (float)dy * s3;
                    wx  += (float)dx * s3;
                }
            }
            float den = tot + SAM_EPS_F;
            float s = (shh - sl) / den;
            fy = ((float)y + wy / den) * (1.0f / (float)HH);
            fx = ((float)x + wx / den) * (1.0f / (float)WW);
            a = s * (1.0f / 2048.0f);   // MR_SIZE / min(H,W) * s
        }
        float* o = out + k + 6 * rank;  // full_A row-major [k,2,3]
        o[0] = a;    o[1] = 0.0f; o[2] = fx;
        o[3] = 0.0f; o[4] = a;    o[5] = fy;
    }
    // degenerate fill (nc < k never happens with this data, but be safe)
    if (i >= ncc && i < k) {
        out[i] = 0.0f;
        float* o = out + k + 6 * i;
        o[0] = 0.0f; o[1] = 0.0f; o[2] = 0.0f;
        o[3] = 0.0f; o[4] = 0.0f; o[5] = 0.0f;
    }
}

extern "C" void kernel_launch(void* const* d_in, const int* in_sizes, int n_in,
                              void* d_out, int out_size) {
    const float* low  = (const float*)d_in[0];
    const float* cur  = (const float*)d_in[1];
    const float* high = (const float*)d_in[2];
    float* out = (float*)d_out;
    int k = out_size / 7;   // out = [topk(k); full_A(k*6)]
    if (k < 1) k = 1;

    reset_kernel<<<2, 1024>>>();
    nms_kernel<<<256, 256>>>(low, cur, high);
    thresh_kernel<<<1, 1024>>>(k);
    compact_kernel<<<512, 256>>>();

    cudaFuncSetAttribute(rank_kernel,
                         cudaFuncAttributeMaxDynamicSharedMemorySize,
                         CAP * (int)sizeof(unsigned long long));
    rank_kernel<<<CAP / 256, 256, CAP * sizeof(unsigned long long)>>>(low, cur, high, out, k);
}

// round 17
// speedup vs baseline: 1.4638x; 1.0619x over previous
#include <cuda_runtime.h>
#include <stdint.h>

#define HH 2048
#define WW 2048
#define NPIX (HH*WW)
#define HBINS 2048
#define CAP 8192
#define SLCAP 4608
#define SURV_MAX (NPIX/2)
#define NMS_EPS_F 1e-5f
#define SAM_EPS_F 1e-8f

// Scratch (device globals — no allocation allowed)
__device__ unsigned long long g_surv[SURV_MAX];
__device__ unsigned long long g_cand[CAP];
__device__ unsigned int g_hist[HBINS];
__device__ unsigned int g_nsurv;
__device__ unsigned int g_ncand;
__device__ unsigned int g_bin;

__device__ __forceinline__ int val_bin(float v) {
    int b = (int)(v * (float)HBINS);
    if (b > HBINS - 1) b = HBINS - 1;
    if (b < 0) b = 0;
    return b;
}

__device__ __forceinline__ unsigned long long make_key(float v, unsigned int idx) {
    return ((unsigned long long)__float_as_uint(v) << 32) |
           (unsigned long long)(0xFFFFFFFFu - idx);
}

__global__ void reset_kernel() {
    int t = blockIdx.x * blockDim.x + threadIdx.x;
    if (t < HBINS) g_hist[t] = 0u;
    if (t == 0) { g_nsurv = 0u; g_ncand = 0u; g_bin = 0u; }
}

// Pass 1: 8px x 8rows per thread, rolling separable 3x3 max.
// low/high loaded UNCONDITIONALLY as float4 pairs (no dependent lazy probes).
// Survivors appended to smem list via warp-ballot aggregation (no thread-
// local buffer -> no local-memory spill).
__global__ void __launch_bounds__(256) nms_kernel(const float* __restrict__ low,
                                                  const float* __restrict__ cur,
                                                  const float* __restrict__ high) {
    __shared__ unsigned long long slist[SLCAP];
    __shared__ unsigned int scount;
    __shared__ unsigned int sbase;
    int t = threadIdx.x;
    unsigned int lane = t & 31;
    if (t == 0) scount = 0u;
    __syncthreads();

    int x0 = t * 8;                 // 256 threads cover full width
    int y0 = blockIdx.x * 8;        // 256 blocks cover full height
    const bool xlo = (x0 == 0), xhi = (x0 + 8 == WW);

    float hmbuf[3][8];
    float cA[8], cB[8];

#define LOADHM(RIDX, SLOT) do {                                              \
    float v[10];                                                             \
    int r_ = (RIDX);                                                         \
    if (r_ >= 0 && r_ < HH) {                                                \
        const float* rp = cur + r_ * WW + x0;                                \
        float4 a4 = *(const float4*)rp;                                      \
        float4 b4 = *(const float4*)(rp + 4);                                \
        v[0] = xlo ? 0.0f : rp[-1];                                          \
        v[1] = a4.x; v[2] = a4.y; v[3] = a4.z; v[4] = a4.w;                  \
        v[5] = b4.x; v[6] = b4.y; v[7] = b4.z; v[8] = b4.w;                  \
        v[9] = xhi ? 0.0f : rp[8];                                           \
    } else {                                                                 \
        _Pragma("unroll") for (int q = 0; q < 10; q++) v[q] = 0.0f;          \
    }                                                                        \
    float p[9];                                                              \
    _Pragma("unroll") for (int q = 0; q < 9; q++) p[q] = fmaxf(v[q], v[q+1]);\
    _Pragma("unroll") for (int q = 0; q < 8; q++)                            \
        hmbuf[SLOT][q] = fmaxf(p[q], v[q+2]);                                \
    _Pragma("unroll") for (int q = 0; q < 8; q++) cB[q] = v[q+1];            \
} while (0)

    LOADHM(y0 - 1, 0);
    LOADHM(y0,     1);
    #pragma unroll
    for (int q = 0; q < 8; q++) cA[q] = cB[q];

    #pragma unroll
    for (int rr = 0; rr < 8; rr++) {
        LOADHM(y0 + rr + 1, (rr + 2) % 3);
        int y = y0 + rr;
        if (y >= 3 && y < HH - 3) {
            // unconditional coalesced low/high row loads
            float4 l4a = *(const float4*)(low  + y * WW + x0);
            float4 l4b = *(const float4*)(low  + y * WW + x0 + 4);
            float4 h4a = *(const float4*)(high + y * WW + x0);
            float4 h4b = *(const float4*)(high + y * WW + x0 + 4);
            float lv[8] = {l4a.x, l4a.y, l4a.z, l4a.w, l4b.x, l4b.y, l4b.z, l4b.w};
            float hv[8] = {h4a.x, h4a.y, h4a.z, h4a.w, h4b.x, h4b.y, h4b.z, h4b.w};
            #pragma unroll
            for (int j = 0; j < 8; j++) {
                float c = cA[j];
                float m = fmaxf(fmaxf(hmbuf[rr % 3][j], hmbuf[(rr + 1) % 3][j]),
                                hmbuf[(rr + 2) % 3][j]);
                int x = x0 + j;
                // same float expression as reference: (cur - mp + 1e-5) > 0
                bool pred = ((c - m + NMS_EPS_F) > 0.0f) &&
                            (c > lv[j]) && (c > hv[j]) &&
                            (x >= 3) && (x < WW - 3);
                unsigned int mask = __ballot_sync(0xFFFFFFFFu, pred);
                if (mask) {
                    int lead = __ffs(mask) - 1;
                    unsigned int base = 0;
                    if ((int)lane == lead)
                        base = atomicAdd(&scount, (unsigned int)__popc(mask));
                    base = __shfl_sync(0xFFFFFFFFu, base, lead);
                    if (pred) {
                        unsigned int pos = base + __popc(mask & ((1u << lane) - 1u));
                        if (pos < SLCAP)
                            slist[pos] = make_key(c, (unsigned int)(y * WW + x));
                    }
                }
            }
        }
        #pragma unroll
        for (int q = 0; q < 8; q++) cA[q] = cB[q];
    }
#undef LOADHM

    __syncthreads();
    unsigned int cnt = scount;
    if (cnt > SLCAP) cnt = SLCAP;
    if (t == 0 && cnt) sbase = atomicAdd(&g_nsurv, cnt);
    __syncthreads();
    for (unsigned int i = t; i < cnt; i += 256) {
        unsigned long long key = slist[i];
        unsigned int dst = sbase + i;
        if (dst < (unsigned int)SURV_MAX) g_surv[dst] = key;
        float v = __uint_as_float((unsigned int)(key >> 32));
        atomicAdd(&g_hist[val_bin(v)], 1u);
    }
}

// Threshold: max bin B with count(values in bins >= B) >= k.
__global__ void thresh_kernel(int k) {
    __shared__ unsigned int suf[1024];
    __shared__ unsigned int sB;
    int t = threadIdx.x;            // 1024 threads, 2 bins each
    if (t == 0) sB = 0u;
    unsigned int b0 = g_hist[2 * t];
    unsigned int b1 = g_hist[2 * t + 1];
    suf[t] = b0 + b1;
    __syncthreads();
    for (int off = 1; off < 1024; off <<= 1) {
        unsigned int add = (t + off < 1024) ? suf[t + off] : 0u;
        __syncthreads();
        suf[t] += add;
        __syncthreads();
    }
    unsigned int after = (t < 1023) ? suf[t + 1] : 0u;
    int best = -1;
    if (after + b1 >= (unsigned int)k) best = 2 * t + 1;
    else if (after + b1 + b0 >= (unsigned int)k) best = 2 * t;
    if (best >= 0) atomicMax(&sB, (unsigned int)best);
    __syncthreads();
    if (t == 0) g_bin = sB;
}

// Compact survivors with bin >= B into g_cand (warp-aggregated atomics).
__global__ void compact_kernel() {
    unsigned int B = g_bin;
    unsigned int n = g_nsurv;
    if (n > (unsigned int)SURV_MAX) n = (unsigned int)SURV_MAX;
    unsigned int stride = gridDim.x * blockDim.x;
    unsigned int lane = threadIdx.x & 31;
    unsigned int nloop = ((n + stride - 1) / stride) * stride;
    for (unsigned int i = blockIdx.x * blockDim.x + threadIdx.x; i < nloop; i += stride) {
        bool pass = false;
        unsigned long long key = 0ULL;
        if (i < n) {
            key = g_surv[i];
            float v = __uint_as_float((unsigned int)(key >> 32));
            pass = ((unsigned int)val_bin(v) >= B);
        }
        unsigned int mask = __ballot_sync(0xFFFFFFFFu, pass);
        if (mask) {
            int lead = __ffs(mask) - 1;
            unsigned int base = 0;
            if ((int)lane == lead) base = atomicAdd(&g_ncand, (unsigned int)__popc(mask));
            base = __shfl_sync(0xFFFFFFFFu, base, lead);
            unsigned int off = __popc(mask & ((1u << lane) - 1u));
            if (pass && base + off < CAP) g_cand[base + off] = key;
        }
    }
}

// Rank + output: each thread owns one candidate; rank = #keys strictly
// greater (keys unique -> exact sort order). rank<k writes out[rank].
extern __shared__ unsigned long long sk[];
__global__ void rank_kernel(const float* __restrict__ low,
                            const float* __restrict__ cur,
                            const float* __restrict__ high,
                            float* __restrict__ out, int k) {
    int t = threadIdx.x;
    int ncc = (int)g_ncand;
    if (ncc > CAP) ncc = CAP;
    for (int i = t; i < ncc; i += blockDim.x) sk[i] = g_cand[i];
    __syncthreads();

    int i = blockIdx.x * blockDim.x + t;
    unsigned long long my = (i < ncc) ? sk[i] : 0ULL;
    int rank = 0;
    #pragma unroll 8
    for (int j = 0; j < ncc; j++) rank += (sk[j] > my) ? 1 : 0;

    if (i < ncc && rank < k) {
        float val = __uint_as_float((unsigned int)(my >> 32));
        unsigned int idx = 0xFFFFFFFFu - (unsigned int)(my & 0xFFFFFFFFu);
        out[rank] = val;
        float a = 0.0f, fx = 0.0f, fy = 0.0f;
        if (idx < (unsigned int)NPIX) {
            int y = (int)(idx / WW);
            int x = (int)(idx % WW);
            float tot = 0.0f, sl = 0.0f, shh = 0.0f, wy = 0.0f, wx = 0.0f;
            #pragma unroll
            for (int dy = -1; dy <= 1; dy++) {
                #pragma unroll
                for (int dx = -1; dx <= 1; dx++) {
                    int jdx = (y + dy) * WW + (x + dx);
                    float lv = low[jdx];
                    float cv = cur[jdx];
                    float hv = high[jdx];
                    float s3 = lv + cv + hv;
                    tot += s3;
                    sl  += lv;
                    shh += hv;
                    wy  += (float)dy * s3;
                    wx  += (float)dx * s3;
                }
            }
            float den = tot + SAM_EPS_F;
            float s = (shh - sl) / den;
            fy = ((float)y + wy / den) * (1.0f / (float)HH);
            fx = ((float)x + wx / den) * (1.0f / (float)WW);
            a = s * (1.0f / 2048.0f);   // MR_SIZE / min(H,W) * s
        }
        float* o = out + k + 6 * rank;  // full_A row-major [k,2,3]
        o[0] = a;    o[1] = 0.0f; o[2] = fx;
        o[3] = 0.0f; o[4] = a;    o[5] = fy;
    }
    // degenerate fill (nc < k never happens with this data, but be safe)
    if (i >= ncc && i < k) {
        out[i] = 0.0f;
        float* o = out + k + 6 * i;
        o[0] = 0.0f; o[1] = 0.0f; o[2] = 0.0f;
        o[3] = 0.0f; o[4] = 0.0f; o[5] = 0.0f;
    }
}

extern "C" void kernel_launch(void* const* d_in, const int* in_sizes, int n_in,
                              void* d_out, int out_size) {
    const float* low  = (const float*)d_in[0];
    const float* cur  = (const float*)d_in[1];
    const float* high = (const float*)d_in[2];
    float* out = (float*)d_out;
    int k = out_size / 7;   // out = [topk(k); full_A(k*6)]
    if (k < 1) k = 1;

    reset_kernel<<<2, 1024>>>();
    nms_kernel<<<256, 256>>>(low, cur, high);
    thresh_kernel<<<1, 1024>>>(k);
    compact_kernel<<<512, 256>>>();

    cudaFuncSetAttribute(rank_kernel,
                         cudaFuncAttributeMaxDynamicSharedMemorySize,
                         CAP * (int)sizeof(unsigned long long));
    rank_kernel<<<CAP / 256, 256, CAP * sizeof(unsigned long long)>>>(low, cur, high, out, k);
}